// round 15
// baseline (speedup 1.0000x reference)
#include <cuda_runtime.h>
#include <cuda_fp16.h>
#include <math.h>
#include <stdint.h>

// ---------------- problem constants ----------------
#define D_MODEL   256
#define N_HEADS   8
#define HEAD_DIM  32
#define L_TOK     13294
#define BATCH     4
#define M_TOT     (BATCH * L_TOK)   // 53176
#define D_FFN     1024

// ---------------- scratch (static device globals; no allocations) ----------------
__device__ __half g_q16   [(size_t)M_TOT * D_MODEL];
__device__ __half g_mem16 [(size_t)M_TOT * D_MODEL];
__device__ __half g_value16[(size_t)M_TOT * D_MODEL];
__device__ float  g_offs  [(size_t)M_TOT * D_MODEL];
__device__ float  g_awlog [(size_t)M_TOT * 128];
__device__ __half g_acc16 [(size_t)M_TOT * D_MODEL];
__device__ float  g_attn  [(size_t)M_TOT * D_MODEL];
__device__ float  g_x     [(size_t)M_TOT * D_MODEL];
__device__ __half g_x16   [(size_t)M_TOT * D_MODEL];
__device__ __half g_h16   [(size_t)M_TOT * D_FFN];
__device__ float  g_ffn   [(size_t)M_TOT * D_MODEL];
// transposed fp16 weights [N][K]
__device__ __half g_vw16  [256 * 256];
__device__ __half g_offw16[256 * 256];
__device__ __half g_aww16 [128 * 256];
__device__ __half g_outw16[256 * 256];
__device__ __half g_l1w16 [1024 * 256];
__device__ __half g_l2w16 [256 * 1024];

// ---------------- helpers ----------------
__device__ __forceinline__ void mma_f16(float* c, const uint32_t* a, const uint32_t* b) {
    asm volatile(
        "mma.sync.aligned.m16n8k16.row.col.f32.f16.f16.f32 "
        "{%0,%1,%2,%3}, {%4,%5,%6,%7}, {%8,%9}, {%0,%1,%2,%3};\n"
        : "+f"(c[0]), "+f"(c[1]), "+f"(c[2]), "+f"(c[3])
        : "r"(a[0]), "r"(a[1]), "r"(a[2]), "r"(a[3]),
          "r"(b[0]), "r"(b[1]));
}
__device__ __forceinline__ void ldsm_x4(uint32_t* r, uint32_t saddr) {
    asm volatile("ldmatrix.sync.aligned.m8n8.x4.shared.b16 {%0,%1,%2,%3}, [%4];\n"
                 : "=r"(r[0]), "=r"(r[1]), "=r"(r[2]), "=r"(r[3]) : "r"(saddr));
}
__device__ __forceinline__ void ldsm_x2(uint32_t* r, uint32_t saddr) {
    asm volatile("ldmatrix.sync.aligned.m8n8.x2.shared.b16 {%0,%1}, [%2];\n"
                 : "=r"(r[0]), "=r"(r[1]) : "r"(saddr));
}
__device__ __forceinline__ void cp_async16(uint32_t smem_addr, const void* gptr) {
    asm volatile("cp.async.ca.shared.global [%0], [%1], 16;\n"
                 :: "r"(smem_addr), "l"(gptr));
}
__device__ __forceinline__ void cp_async16_guard(uint32_t smem_addr, const void* gptr, int src_bytes) {
    asm volatile("cp.async.ca.shared.global [%0], [%1], 16, %2;\n"
                 :: "r"(smem_addr), "l"(gptr), "r"(src_bytes));
}
__device__ __forceinline__ void cp_commit() { asm volatile("cp.async.commit_group;\n"); }
template<int N>
__device__ __forceinline__ void cp_wait() { asm volatile("cp.async.wait_group %0;\n" :: "n"(N)); }

// ---------------- fused adds: q16 = src+pos, mem16 = src2+memory_pos ----------------
__global__ void add2h2_kernel(const float* __restrict__ a0, const float* __restrict__ b0,
                              const float* __restrict__ a1, const float* __restrict__ b1,
                              __half* __restrict__ o0, __half* __restrict__ o1, int n4)
{
    int i = blockIdx.x * blockDim.x + threadIdx.x;
    if (i < n4) {
        float4 x = ((const float4*)a0)[i];
        float4 y = ((const float4*)b0)[i];
        ((__half2*)o0)[i * 2 + 0] = __floats2half2_rn(x.x + y.x, x.y + y.y);
        ((__half2*)o0)[i * 2 + 1] = __floats2half2_rn(x.z + y.z, x.w + y.w);
        float4 u = ((const float4*)a1)[i];
        float4 v = ((const float4*)b1)[i];
        ((__half2*)o1)[i * 2 + 0] = __floats2half2_rn(u.x + v.x, u.y + v.y);
        ((__half2*)o1)[i * 2 + 1] = __floats2half2_rn(u.z + v.z, u.w + v.w);
    }
}

// ---------------- all 6 weight transposes fp32[K][N] -> fp16[N][K], one launch ----------------
__global__ void transpose6_kernel(
    const float* __restrict__ i0, const float* __restrict__ i1, const float* __restrict__ i2,
    const float* __restrict__ i3, const float* __restrict__ i4, const float* __restrict__ i5,
    __half* __restrict__ o0, __half* __restrict__ o1, __half* __restrict__ o2,
    __half* __restrict__ o3, __half* __restrict__ o4, __half* __restrict__ o5)
{
    const float* in; __half* out; int K, N;
    switch (blockIdx.z) {
        case 0: in = i0; out = o0; K = 256;  N = 256;  break;
        case 1: in = i1; out = o1; K = 256;  N = 256;  break;
        case 2: in = i2; out = o2; K = 256;  N = 128;  break;
        case 3: in = i3; out = o3; K = 256;  N = 256;  break;
        case 4: in = i4; out = o4; K = 256;  N = 1024; break;
        default: in = i5; out = o5; K = 1024; N = 256; break;
    }
    int n0 = blockIdx.x * 32, k0 = blockIdx.y * 32;
    if (n0 >= N || k0 >= K) return;

    __shared__ float t[32][33];
    int tx = threadIdx.x, ty = threadIdx.y;      // 32 x 8
#pragma unroll
    for (int i = ty; i < 32; i += 8)
        t[i][tx] = in[(size_t)(k0 + i) * N + n0 + tx];
    __syncthreads();
#pragma unroll
    for (int i = ty; i < 32; i += 8)
        out[(size_t)(n0 + i) * K + k0 + tx] = __float2half(t[tx][i]);
}

// ---------------- FP16 tensor-core GEMM, 2-stage cp.async, ldmatrix ----------------
#define LDH 56
#define ASZH (128 * LDH)
#define BSZH (128 * LDH)
#define SMEM_BYTES ((2 * ASZH + 2 * BSZH) * 2)

template<int RELU, int HOUT>
__global__ __launch_bounds__(256, 3)
void hgemm_kernel(const __half* __restrict__ A, const __half* __restrict__ Wt,
                  const float* __restrict__ bias, void* __restrict__ Cout,
                  int M, int N, int K)
{
    extern __shared__ __half smem[];
    __half* As = smem;                 // [2][128][LDH]
    __half* Bs = smem + 2 * ASZH;      // [2][128][LDH]

    const int tid  = threadIdx.x;
    const int lane = tid & 31;
    const int warp = tid >> 5;
    const int wm = (warp >> 2) * 64;
    const int wn = (warp & 3) * 32;
    const int grp = lane >> 2;
    const int tg  = lane & 3;
    const int m0 = blockIdx.y * 128;
    const int n0 = blockIdx.x * 128;

    uint32_t As_u = (uint32_t)__cvta_generic_to_shared(As);
    uint32_t Bs_u = (uint32_t)__cvta_generic_to_shared(Bs);

    float acc[4][4][4];
#pragma unroll
    for (int mi = 0; mi < 4; mi++)
#pragma unroll
        for (int ni = 0; ni < 4; ni++)
#pragma unroll
            for (int e = 0; e < 4; e++) acc[mi][ni][e] = 0.0f;

    const int T = K / 32;

    auto fill = [&](int st, int k0) {
        uint32_t abase = As_u + (uint32_t)(st * ASZH * 2);
        uint32_t bbase = Bs_u + (uint32_t)(st * BSZH * 2);
#pragma unroll
        for (int it = 0; it < 2; it++) {
            int idx = tid + it * 256;
            int r  = idx >> 2;
            int kc = idx & 3;
            int valid = (m0 + r < M) ? 16 : 0;
            cp_async16_guard(abase + (uint32_t)(r * 112 + kc * 16),
                             A + (size_t)(m0 + r) * K + k0 + kc * 8, valid);
        }
#pragma unroll
        for (int it = 0; it < 2; it++) {
            int idx = tid + it * 256;
            int r  = idx >> 2;
            int kc = idx & 3;
            cp_async16(bbase + (uint32_t)(r * 112 + kc * 16),
                       Wt + (size_t)(n0 + r) * K + k0 + kc * 8);
        }
        cp_commit();
    };

    fill(0, 0);

    for (int t = 0; t < T; t++) {
        if (t + 1 < T) {
            fill((t + 1) & 1, (t + 1) * 32);
            cp_wait<1>();
        } else {
            cp_wait<0>();
        }
        __syncthreads();

        const uint32_t As_sb = As_u + (uint32_t)((t & 1) * ASZH * 2);
        const uint32_t Bs_sb = Bs_u + (uint32_t)((t & 1) * BSZH * 2);

#pragma unroll
        for (int ks = 0; ks < 2; ks++) {
            const int kb = ks * 16;
            uint32_t a[4][4], b[4][2];
#pragma unroll
            for (int mi = 0; mi < 4; mi++) {
                uint32_t ad = As_sb + (uint32_t)(((wm + mi * 16 + (lane & 15)) * LDH
                                                 + kb + (lane >> 4) * 8) * 2);
                ldsm_x4(a[mi], ad);
            }
#pragma unroll
            for (int ni = 0; ni < 4; ni++) {
                uint32_t bd = Bs_sb + (uint32_t)(((wn + ni * 8 + (lane & 7)) * LDH
                                                 + kb + ((lane >> 3) & 1) * 8) * 2);
                ldsm_x2(b[ni], bd);
            }
#pragma unroll
            for (int mi = 0; mi < 4; mi++)
#pragma unroll
                for (int ni = 0; ni < 4; ni++)
                    mma_f16(acc[mi][ni], a[mi], b[ni]);
        }
        __syncthreads();
    }

    // epilogue
#pragma unroll
    for (int mi = 0; mi < 4; mi++) {
        int r0 = m0 + wm + mi * 16 + grp;
        int r1 = r0 + 8;
#pragma unroll
        for (int ni = 0; ni < 4; ni++) {
            int col = n0 + wn + ni * 8 + tg * 2;
            float bx = bias[col], by = bias[col + 1];
            float* cc = acc[mi][ni];
            float v0x = cc[0] + bx, v0y = cc[1] + by;
            float v1x = cc[2] + bx, v1y = cc[3] + by;
            if (RELU) {
                v0x = fmaxf(v0x, 0.f); v0y = fmaxf(v0y, 0.f);
                v1x = fmaxf(v1x, 0.f); v1y = fmaxf(v1y, 0.f);
            }
            if (HOUT) {
                __half* C16 = (__half*)Cout;
                if (r0 < M) *(__half2*)(C16 + (size_t)r0 * N + col) = __floats2half2_rn(v0x, v0y);
                if (r1 < M) *(__half2*)(C16 + (size_t)r1 * N + col) = __floats2half2_rn(v1x, v1y);
            } else {
                float* C = (float*)Cout;
                if (r0 < M) { float2 o; o.x = v0x; o.y = v0y; *(float2*)(C + (size_t)r0 * N + col) = o; }
                if (r1 < M) { float2 o; o.x = v1x; o.y = v1y; *(float2*)(C + (size_t)r1 * N + col) = o; }
            }
        }
    }
}

// ---------------- deformable attention sampling (softmax fused) ----------------
// Lane-parallel setup: lanes 0-15 each handle one (level,point): load logit,
// butterfly softmax over the 16 lanes, compute 4 clamped indices + 4 fused
// weights. Inner loop shuffles to all lanes; unconditional clamped loads.
__global__ __launch_bounds__(256)
void deform_sample_kernel(const __half* __restrict__ value16,
                          const float* __restrict__ offs,
                          const float* __restrict__ awlog,
                          __half* __restrict__ acc16)
{
    const int bq = blockIdx.x;
    const int h    = threadIdx.x >> 5;
    const int lane = threadIdx.x & 31;

    const int b  = bq / L_TOK;
    const int qi = bq - b * L_TOK;

    int ql, s;
    if      (qi < 10000) { ql = 0; s = 0;     }
    else if (qi < 12500) { ql = 1; s = 10000; }
    else if (qi < 13125) { ql = 2; s = 12500; }
    else                 { ql = 3; s = 13125; }
    const int LH[4] = {100, 50, 25, 13};
    const int LS[4] = {0, 10000, 12500, 13125};
    const int Wq = LH[ql];
    int rem = qi - s;
    float refx = ((rem % Wq) + 0.5f) / (float)Wq;
    float refy = ((rem / Wq) + 0.5f) / (float)Wq;

    // per-point setup (lanes 16-31 duplicate lanes 0-15; harmless)
    const int pidx = lane & 15;
    const int l  = pidx >> 2;
    const int Wl = LH[l];
    const int Sl = LS[l];
    const float Wf = (float)Wl;

    // fused softmax over this head's 16 logits (butterfly within 16-lane group)
    float lg = awlog[(size_t)bq * 128 + h * 16 + pidx];
    float m = lg;
#pragma unroll
    for (int o = 8; o; o >>= 1) m = fmaxf(m, __shfl_xor_sync(0xFFFFFFFFu, m, o));
    float ev = expf(lg - m);
    float ssum = ev;
#pragma unroll
    for (int o = 8; o; o >>= 1) ssum += __shfl_xor_sync(0xFFFFFFFFu, ssum, o);
    float aw = ev / ssum;

    float2 oxy = *(const float2*)(offs + (size_t)bq * 256 + h * 32 + pidx * 2);

    float locx = refx + oxy.x / Wf;
    float locy = refy + oxy.y / Wf;
    float x = locx * Wf - 0.5f;
    float y = locy * Wf - 0.5f;
    float x0f = floorf(x), y0f = floorf(y);
    float wx1 = x - x0f,   wy1 = y - y0f;
    float wx0 = 1.0f - wx1, wy0 = 1.0f - wy1;
    int ix0 = (int)x0f, iy0 = (int)y0f;
    int ix1 = ix0 + 1,  iy1 = iy0 + 1;
    float fx0 = (ix0 >= 0 && ix0 < Wl) ? 1.f : 0.f;
    float fx1 = (ix1 >= 0 && ix1 < Wl) ? 1.f : 0.f;
    float fy0 = (iy0 >= 0 && iy0 < Wl) ? 1.f : 0.f;
    float fy1 = (iy1 >= 0 && iy1 < Wl) ? 1.f : 0.f;
    int cx0 = min(max(ix0, 0), Wl - 1);
    int cx1 = min(max(ix1, 0), Wl - 1);
    int cy0 = min(max(iy0, 0), Wl - 1);
    int cy1 = min(max(iy1, 0), Wl - 1);
    int i00 = (Sl + cy0 * Wl + cx0) * 256;
    int i01 = (Sl + cy0 * Wl + cx1) * 256;
    int i10 = (Sl + cy1 * Wl + cx0) * 256;
    int i11 = (Sl + cy1 * Wl + cx1) * 256;
    float w00 = wy0 * wx0 * aw * (fy0 * fx0);
    float w01 = wy0 * wx1 * aw * (fy0 * fx1);
    float w10 = wy1 * wx0 * aw * (fy1 * fx0);
    float w11 = wy1 * wx1 * aw * (fy1 * fx1);

    const __half* vbase = value16 + (size_t)b * L_TOK * 256 + h * 32 + lane;

    float a = 0.0f;
#pragma unroll
    for (int p = 0; p < 16; p++) {
        int   j00 = __shfl_sync(0xFFFFFFFFu, i00, p);
        int   j01 = __shfl_sync(0xFFFFFFFFu, i01, p);
        int   j10 = __shfl_sync(0xFFFFFFFFu, i10, p);
        int   j11 = __shfl_sync(0xFFFFFFFFu, i11, p);
        float u00 = __shfl_sync(0xFFFFFFFFu, w00, p);
        float u01 = __shfl_sync(0xFFFFFFFFu, w01, p);
        float u10 = __shfl_sync(0xFFFFFFFFu, w10, p);
        float u11 = __shfl_sync(0xFFFFFFFFu, w11, p);
        float v00 = __half2float(vbase[j00]);
        float v01 = __half2float(vbase[j01]);
        float v10 = __half2float(vbase[j10]);
        float v11 = __half2float(vbase[j11]);
        a = fmaf(v00, u00, a);
        a = fmaf(v01, u01, a);
        a = fmaf(v10, u10, a);
        a = fmaf(v11, u11, a);
    }
    acc16[(size_t)bq * 256 + h * 32 + lane] = __float2half(a);
}

// ---------------- fused residual + LayerNorm (optional fp16 copy) ----------------
__global__ __launch_bounds__(256)
void ln_kernel(const float* __restrict__ a, const float* __restrict__ r,
               const float* __restrict__ g, const float* __restrict__ be,
               float* __restrict__ out, __half* __restrict__ out16)
{
    int row  = blockIdx.x * 8 + (threadIdx.x >> 5);
    int lane = threadIdx.x & 31;
    if (row >= M_TOT) return;

    const float4* pa = (const float4*)(a + (size_t)row * 256);
    const float4* pr = (const float4*)(r + (size_t)row * 256);
    float4 v0 = pa[lane],      w0 = pr[lane];
    float4 v1 = pa[32 + lane], w1 = pr[32 + lane];
    v0.x += w0.x; v0.y += w0.y; v0.z += w0.z; v0.w += w0.w;
    v1.x += w1.x; v1.y += w1.y; v1.z += w1.z; v1.w += w1.w;

    float ssum = v0.x + v0.y + v0.z + v0.w + v1.x + v1.y + v1.z + v1.w;
#pragma unroll
    for (int o = 16; o; o >>= 1) ssum += __shfl_xor_sync(0xFFFFFFFFu, ssum, o);
    float mu = ssum * (1.0f / 256.0f);

    float d0x = v0.x - mu, d0y = v0.y - mu, d0z = v0.z - mu, d0w = v0.w - mu;
    float d1x = v1.x - mu, d1y = v1.y - mu, d1z = v1.z - mu, d1w = v1.w - mu;
    float sq = d0x*d0x + d0y*d0y + d0z*d0z + d0w*d0w
             + d1x*d1x + d1y*d1y + d1z*d1z + d1w*d1w;
#pragma unroll
    for (int o = 16; o; o >>= 1) sq += __shfl_xor_sync(0xFFFFFFFFu, sq, o);
    float var = sq * (1.0f / 256.0f);
    float sc = rsqrtf(var + 1e-5f);

    const float4* pg = (const float4*)g;
    const float4* pb = (const float4*)be;
    float4 g0 = pg[lane], g1 = pg[32 + lane];
    float4 b0 = pb[lane], b1 = pb[32 + lane];

    float4 o0, o1;
    o0.x = d0x * sc * g0.x + b0.x;  o0.y = d0y * sc * g0.y + b0.y;
    o0.z = d0z * sc * g0.z + b0.z;  o0.w = d0w * sc * g0.w + b0.w;
    o1.x = d1x * sc * g1.x + b1.x;  o1.y = d1y * sc * g1.y + b1.y;
    o1.z = d1z * sc * g1.z + b1.z;  o1.w = d1w * sc * g1.w + b1.w;

    float4* po = (float4*)(out + (size_t)row * 256);
    po[lane]      = o0;
    po[32 + lane] = o1;

    if (out16) {
        __half2* ph = (__half2*)(out16 + (size_t)row * 256);
        ph[lane * 2 + 0]      = __floats2half2_rn(o0.x, o0.y);
        ph[lane * 2 + 1]      = __floats2half2_rn(o0.z, o0.w);
        ph[64 + lane * 2 + 0] = __floats2half2_rn(o1.x, o1.y);
        ph[64 + lane * 2 + 1] = __floats2half2_rn(o1.z, o1.w);
    }
}

// ---------------- launch ----------------
extern "C" void kernel_launch(void* const* d_in, const int* in_sizes, int n_in,
                              void* d_out, int out_size)
{
    const float* src        = (const float*)d_in[0];
    const float* src2       = (const float*)d_in[1];
    const float* pos        = (const float*)d_in[2];
    const float* memory_pos = (const float*)d_in[3];
    const float* value_w    = (const float*)d_in[4];
    const float* value_b    = (const float*)d_in[5];
    const float* off_w      = (const float*)d_in[6];
    const float* off_b      = (const float*)d_in[7];
    const float* aw_w       = (const float*)d_in[8];
    const float* aw_b       = (const float*)d_in[9];
    const float* out_w      = (const float*)d_in[10];
    const float* out_b      = (const float*)d_in[11];
    const float* ln_g       = (const float*)d_in[12];
    const float* ln_b       = (const float*)d_in[13];
    const float* lin1_w     = (const float*)d_in[14];
    const float* lin1_b     = (const float*)d_in[15];
    const float* lin2_w     = (const float*)d_in[16];
    const float* lin2_b     = (const float*)d_in[17];
    float* outp = (float*)d_out;

    __half *q16, *mem16, *value16, *acc16, *x16, *h16;
    __half *vw16, *offw16, *aww16, *outw16, *l1w16, *l2w16;
    float *offs, *awlog, *attn, *x, *ffn;
    cudaGetSymbolAddress((void**)&q16,    g_q16);
    cudaGetSymbolAddress((void**)&mem16,  g_mem16);
    cudaGetSymbolAddress((void**)&value16,g_value16);
    cudaGetSymbolAddress((void**)&offs,   g_offs);
    cudaGetSymbolAddress((void**)&awlog,  g_awlog);
    cudaGetSymbolAddress((void**)&acc16,  g_acc16);
    cudaGetSymbolAddress((void**)&attn,   g_attn);
    cudaGetSymbolAddress((void**)&x,      g_x);
    cudaGetSymbolAddress((void**)&x16,    g_x16);
    cudaGetSymbolAddress((void**)&h16,    g_h16);
    cudaGetSymbolAddress((void**)&ffn,    g_ffn);
    cudaGetSymbolAddress((void**)&vw16,   g_vw16);
    cudaGetSymbolAddress((void**)&offw16, g_offw16);
    cudaGetSymbolAddress((void**)&aww16,  g_aww16);
    cudaGetSymbolAddress((void**)&outw16, g_outw16);
    cudaGetSymbolAddress((void**)&l1w16,  g_l1w16);
    cudaGetSymbolAddress((void**)&l2w16,  g_l2w16);

    cudaFuncSetAttribute(hgemm_kernel<0,0>, cudaFuncAttributeMaxDynamicSharedMemorySize, SMEM_BYTES);
    cudaFuncSetAttribute(hgemm_kernel<0,1>, cudaFuncAttributeMaxDynamicSharedMemorySize, SMEM_BYTES);
    cudaFuncSetAttribute(hgemm_kernel<1,1>, cudaFuncAttributeMaxDynamicSharedMemorySize, SMEM_BYTES);

    transpose6_kernel<<<dim3(32, 32, 6), dim3(32, 8)>>>(
        value_w, off_w, aw_w, out_w, lin1_w, lin2_w,
        vw16, offw16, aww16, outw16, l1w16, l2w16);

    const int n4 = M_TOT * D_MODEL / 4;
    add2h2_kernel<<<(n4 + 255) / 256, 256>>>(src, pos, src2, memory_pos, q16, mem16, n4);

    dim3 blk(256);
    const int GY = (M_TOT + 127) / 128;     // 416
    dim3 g256(2, GY);
    dim3 g128(1, GY);
    dim3 g1024(8, GY);

    hgemm_kernel<0,1><<<g256, blk, SMEM_BYTES>>>(mem16, vw16,   value_b, value16, M_TOT, 256, 256);
    hgemm_kernel<0,0><<<g256, blk, SMEM_BYTES>>>(q16,   offw16, off_b,   offs,    M_TOT, 256, 256);
    hgemm_kernel<0,0><<<g128, blk, SMEM_BYTES>>>(q16,   aww16,  aw_b,    awlog,   M_TOT, 128, 256);

    deform_sample_kernel<<<M_TOT, 256>>>(value16, offs, awlog, acc16);

    hgemm_kernel<0,0><<<g256, blk, SMEM_BYTES>>>(acc16, outw16, out_b, attn, M_TOT, 256, 256);

    ln_kernel<<<(M_TOT + 7) / 8, 256>>>(attn, src, ln_g, ln_b, x, x16);

    hgemm_kernel<1,1><<<g1024, blk, SMEM_BYTES>>>(x16, l1w16, lin1_b, h16, M_TOT, 1024, 256);
    hgemm_kernel<0,0><<<g256,  blk, SMEM_BYTES>>>(h16, l2w16, lin2_b, ffn,  M_TOT, 256, 1024);

    ln_kernel<<<(M_TOT + 7) / 8, 256>>>(ffn, x, ln_g, ln_b, outp, (half*)nullptr);
}

// round 16
// speedup vs baseline: 1.3045x; 1.3045x over previous
#include <cuda_runtime.h>
#include <cuda_fp16.h>
#include <math.h>
#include <stdint.h>

// ---------------- problem constants ----------------
#define D_MODEL   256
#define N_HEADS   8
#define HEAD_DIM  32
#define L_TOK     13294
#define BATCH     4
#define M_TOT     (BATCH * L_TOK)   // 53176
#define D_FFN     1024

// ---------------- scratch (static device globals; no allocations) ----------------
__device__ __half g_q16   [(size_t)M_TOT * D_MODEL];
__device__ __half g_mem16 [(size_t)M_TOT * D_MODEL];
__device__ __half g_value16[(size_t)M_TOT * D_MODEL];
__device__ float  g_offs  [(size_t)M_TOT * D_MODEL];
__device__ float  g_awlog [(size_t)M_TOT * 128];
__device__ __half g_acc16 [(size_t)M_TOT * D_MODEL];
__device__ float  g_attn  [(size_t)M_TOT * D_MODEL];
__device__ float  g_x     [(size_t)M_TOT * D_MODEL];
__device__ __half g_x16   [(size_t)M_TOT * D_MODEL];
__device__ __half g_h16   [(size_t)M_TOT * D_FFN];
__device__ float  g_ffn   [(size_t)M_TOT * D_MODEL];
// transposed fp16 weights [N][K]
__device__ __half g_vw16  [256 * 256];
__device__ __half g_offw16[256 * 256];
__device__ __half g_aww16 [128 * 256];
__device__ __half g_outw16[256 * 256];
__device__ __half g_l1w16 [1024 * 256];
__device__ __half g_l2w16 [256 * 1024];

// ---------------- helpers ----------------
__device__ __forceinline__ void mma_f16(float* c, const uint32_t* a, const uint32_t* b) {
    asm volatile(
        "mma.sync.aligned.m16n8k16.row.col.f32.f16.f16.f32 "
        "{%0,%1,%2,%3}, {%4,%5,%6,%7}, {%8,%9}, {%0,%1,%2,%3};\n"
        : "+f"(c[0]), "+f"(c[1]), "+f"(c[2]), "+f"(c[3])
        : "r"(a[0]), "r"(a[1]), "r"(a[2]), "r"(a[3]),
          "r"(b[0]), "r"(b[1]));
}
__device__ __forceinline__ void ldsm_x4(uint32_t* r, uint32_t saddr) {
    asm volatile("ldmatrix.sync.aligned.m8n8.x4.shared.b16 {%0,%1,%2,%3}, [%4];\n"
                 : "=r"(r[0]), "=r"(r[1]), "=r"(r[2]), "=r"(r[3]) : "r"(saddr));
}
__device__ __forceinline__ void ldsm_x2(uint32_t* r, uint32_t saddr) {
    asm volatile("ldmatrix.sync.aligned.m8n8.x2.shared.b16 {%0,%1}, [%2];\n"
                 : "=r"(r[0]), "=r"(r[1]) : "r"(saddr));
}
__device__ __forceinline__ void cp_async16(uint32_t smem_addr, const void* gptr) {
    asm volatile("cp.async.ca.shared.global [%0], [%1], 16;\n"
                 :: "r"(smem_addr), "l"(gptr));
}
__device__ __forceinline__ void cp_async16_guard(uint32_t smem_addr, const void* gptr, int src_bytes) {
    asm volatile("cp.async.ca.shared.global [%0], [%1], 16, %2;\n"
                 :: "r"(smem_addr), "l"(gptr), "r"(src_bytes));
}
__device__ __forceinline__ void cp_commit() { asm volatile("cp.async.commit_group;\n"); }
template<int N>
__device__ __forceinline__ void cp_wait() { asm volatile("cp.async.wait_group %0;\n" :: "n"(N)); }

// ---------------- fused adds: q16 = src+pos, mem16 = src2+memory_pos ----------------
__global__ void add2h2_kernel(const float* __restrict__ a0, const float* __restrict__ b0,
                              const float* __restrict__ a1, const float* __restrict__ b1,
                              __half* __restrict__ o0, __half* __restrict__ o1, int n4)
{
    int i = blockIdx.x * blockDim.x + threadIdx.x;
    if (i < n4) {
        float4 x = ((const float4*)a0)[i];
        float4 y = ((const float4*)b0)[i];
        ((__half2*)o0)[i * 2 + 0] = __floats2half2_rn(x.x + y.x, x.y + y.y);
        ((__half2*)o0)[i * 2 + 1] = __floats2half2_rn(x.z + y.z, x.w + y.w);
        float4 u = ((const float4*)a1)[i];
        float4 v = ((const float4*)b1)[i];
        ((__half2*)o1)[i * 2 + 0] = __floats2half2_rn(u.x + v.x, u.y + v.y);
        ((__half2*)o1)[i * 2 + 1] = __floats2half2_rn(u.z + v.z, u.w + v.w);
    }
}

// ---------------- all 6 weight transposes fp32[K][N] -> fp16[N][K], one launch ----------------
__global__ void transpose6_kernel(
    const float* __restrict__ i0, const float* __restrict__ i1, const float* __restrict__ i2,
    const float* __restrict__ i3, const float* __restrict__ i4, const float* __restrict__ i5,
    __half* __restrict__ o0, __half* __restrict__ o1, __half* __restrict__ o2,
    __half* __restrict__ o3, __half* __restrict__ o4, __half* __restrict__ o5)
{
    const float* in; __half* out; int K, N;
    switch (blockIdx.z) {
        case 0: in = i0; out = o0; K = 256;  N = 256;  break;
        case 1: in = i1; out = o1; K = 256;  N = 256;  break;
        case 2: in = i2; out = o2; K = 256;  N = 128;  break;
        case 3: in = i3; out = o3; K = 256;  N = 256;  break;
        case 4: in = i4; out = o4; K = 256;  N = 1024; break;
        default: in = i5; out = o5; K = 1024; N = 256; break;
    }
    int n0 = blockIdx.x * 32, k0 = blockIdx.y * 32;
    if (n0 >= N || k0 >= K) return;

    __shared__ float t[32][33];
    int tx = threadIdx.x, ty = threadIdx.y;      // 32 x 8
#pragma unroll
    for (int i = ty; i < 32; i += 8)
        t[i][tx] = in[(size_t)(k0 + i) * N + n0 + tx];
    __syncthreads();
#pragma unroll
    for (int i = ty; i < 32; i += 8)
        out[(size_t)(n0 + i) * K + k0 + tx] = __float2half(t[tx][i]);
}

// ---------------- FP16 tensor-core GEMM, 2-stage cp.async, ldmatrix ----------------
#define LDH 56
#define ASZH (128 * LDH)
#define BSZH (128 * LDH)
#define SMEM_BYTES ((2 * ASZH + 2 * BSZH) * 2)

template<int RELU, int HOUT>
__global__ __launch_bounds__(256)
void hgemm_kernel(const __half* __restrict__ A, const __half* __restrict__ Wt,
                  const float* __restrict__ bias, void* __restrict__ Cout,
                  int M, int N, int K)
{
    extern __shared__ __half smem[];
    __half* As = smem;                 // [2][128][LDH]
    __half* Bs = smem + 2 * ASZH;      // [2][128][LDH]

    const int tid  = threadIdx.x;
    const int lane = tid & 31;
    const int warp = tid >> 5;
    const int wm = (warp >> 2) * 64;
    const int wn = (warp & 3) * 32;
    const int grp = lane >> 2;
    const int tg  = lane & 3;
    const int m0 = blockIdx.y * 128;
    const int n0 = blockIdx.x * 128;

    uint32_t As_u = (uint32_t)__cvta_generic_to_shared(As);
    uint32_t Bs_u = (uint32_t)__cvta_generic_to_shared(Bs);

    float acc[4][4][4];
#pragma unroll
    for (int mi = 0; mi < 4; mi++)
#pragma unroll
        for (int ni = 0; ni < 4; ni++)
#pragma unroll
            for (int e = 0; e < 4; e++) acc[mi][ni][e] = 0.0f;

    const int T = K / 32;

    auto fill = [&](int st, int k0) {
        uint32_t abase = As_u + (uint32_t)(st * ASZH * 2);
        uint32_t bbase = Bs_u + (uint32_t)(st * BSZH * 2);
#pragma unroll
        for (int it = 0; it < 2; it++) {
            int idx = tid + it * 256;
            int r  = idx >> 2;
            int kc = idx & 3;
            int valid = (m0 + r < M) ? 16 : 0;
            cp_async16_guard(abase + (uint32_t)(r * 112 + kc * 16),
                             A + (size_t)(m0 + r) * K + k0 + kc * 8, valid);
        }
#pragma unroll
        for (int it = 0; it < 2; it++) {
            int idx = tid + it * 256;
            int r  = idx >> 2;
            int kc = idx & 3;
            cp_async16(bbase + (uint32_t)(r * 112 + kc * 16),
                       Wt + (size_t)(n0 + r) * K + k0 + kc * 8);
        }
        cp_commit();
    };

    fill(0, 0);

    for (int t = 0; t < T; t++) {
        if (t + 1 < T) {
            fill((t + 1) & 1, (t + 1) * 32);
            cp_wait<1>();
        } else {
            cp_wait<0>();
        }
        __syncthreads();

        const uint32_t As_sb = As_u + (uint32_t)((t & 1) * ASZH * 2);
        const uint32_t Bs_sb = Bs_u + (uint32_t)((t & 1) * BSZH * 2);

#pragma unroll
        for (int ks = 0; ks < 2; ks++) {
            const int kb = ks * 16;
            uint32_t a[4][4], b[4][2];
#pragma unroll
            for (int mi = 0; mi < 4; mi++) {
                uint32_t ad = As_sb + (uint32_t)(((wm + mi * 16 + (lane & 15)) * LDH
                                                 + kb + (lane >> 4) * 8) * 2);
                ldsm_x4(a[mi], ad);
            }
#pragma unroll
            for (int ni = 0; ni < 4; ni++) {
                uint32_t bd = Bs_sb + (uint32_t)(((wn + ni * 8 + (lane & 7)) * LDH
                                                 + kb + ((lane >> 3) & 1) * 8) * 2);
                ldsm_x2(b[ni], bd);
            }
#pragma unroll
            for (int mi = 0; mi < 4; mi++)
#pragma unroll
                for (int ni = 0; ni < 4; ni++)
                    mma_f16(acc[mi][ni], a[mi], b[ni]);
        }
        __syncthreads();
    }

    // epilogue
#pragma unroll
    for (int mi = 0; mi < 4; mi++) {
        int r0 = m0 + wm + mi * 16 + grp;
        int r1 = r0 + 8;
#pragma unroll
        for (int ni = 0; ni < 4; ni++) {
            int col = n0 + wn + ni * 8 + tg * 2;
            float bx = bias[col], by = bias[col + 1];
            float* cc = acc[mi][ni];
            float v0x = cc[0] + bx, v0y = cc[1] + by;
            float v1x = cc[2] + bx, v1y = cc[3] + by;
            if (RELU) {
                v0x = fmaxf(v0x, 0.f); v0y = fmaxf(v0y, 0.f);
                v1x = fmaxf(v1x, 0.f); v1y = fmaxf(v1y, 0.f);
            }
            if (HOUT) {
                __half* C16 = (__half*)Cout;
                if (r0 < M) *(__half2*)(C16 + (size_t)r0 * N + col) = __floats2half2_rn(v0x, v0y);
                if (r1 < M) *(__half2*)(C16 + (size_t)r1 * N + col) = __floats2half2_rn(v1x, v1y);
            } else {
                float* C = (float*)Cout;
                if (r0 < M) { float2 o; o.x = v0x; o.y = v0y; *(float2*)(C + (size_t)r0 * N + col) = o; }
                if (r1 < M) { float2 o; o.x = v1x; o.y = v1y; *(float2*)(C + (size_t)r1 * N + col) = o; }
            }
        }
    }
}

// ---------------- deformable attention sampling (softmax fused) ----------------
// Lane-parallel setup: lanes 0-15 each handle one (level,point): load logit,
// butterfly softmax over the 16 lanes, compute 4 clamped indices + 4 fused
// weights. Inner loop shuffles to all lanes; unconditional clamped loads.
__global__ __launch_bounds__(256)
void deform_sample_kernel(const __half* __restrict__ value16,
                          const float* __restrict__ offs,
                          const float* __restrict__ awlog,
                          __half* __restrict__ acc16)
{
    const int bq = blockIdx.x;
    const int h    = threadIdx.x >> 5;
    const int lane = threadIdx.x & 31;

    const int b  = bq / L_TOK;
    const int qi = bq - b * L_TOK;

    int ql, s;
    if      (qi < 10000) { ql = 0; s = 0;     }
    else if (qi < 12500) { ql = 1; s = 10000; }
    else if (qi < 13125) { ql = 2; s = 12500; }
    else                 { ql = 3; s = 13125; }
    const int LH[4] = {100, 50, 25, 13};
    const int LS[4] = {0, 10000, 12500, 13125};
    const int Wq = LH[ql];
    int rem = qi - s;
    float refx = ((rem % Wq) + 0.5f) / (float)Wq;
    float refy = ((rem / Wq) + 0.5f) / (float)Wq;

    // per-point setup (lanes 16-31 duplicate lanes 0-15; harmless)
    const int pidx = lane & 15;
    const int l  = pidx >> 2;
    const int Wl = LH[l];
    const int Sl = LS[l];
    const float Wf = (float)Wl;

    // fused softmax over this head's 16 logits (butterfly within 16-lane group)
    float lg = awlog[(size_t)bq * 128 + h * 16 + pidx];
    float m = lg;
#pragma unroll
    for (int o = 8; o; o >>= 1) m = fmaxf(m, __shfl_xor_sync(0xFFFFFFFFu, m, o));
    float ev = expf(lg - m);
    float ssum = ev;
#pragma unroll
    for (int o = 8; o; o >>= 1) ssum += __shfl_xor_sync(0xFFFFFFFFu, ssum, o);
    float aw = ev / ssum;

    float2 oxy = *(const float2*)(offs + (size_t)bq * 256 + h * 32 + pidx * 2);

    float locx = refx + oxy.x / Wf;
    float locy = refy + oxy.y / Wf;
    float x = locx * Wf - 0.5f;
    float y = locy * Wf - 0.5f;
    float x0f = floorf(x), y0f = floorf(y);
    float wx1 = x - x0f,   wy1 = y - y0f;
    float wx0 = 1.0f - wx1, wy0 = 1.0f - wy1;
    int ix0 = (int)x0f, iy0 = (int)y0f;
    int ix1 = ix0 + 1,  iy1 = iy0 + 1;
    float fx0 = (ix0 >= 0 && ix0 < Wl) ? 1.f : 0.f;
    float fx1 = (ix1 >= 0 && ix1 < Wl) ? 1.f : 0.f;
    float fy0 = (iy0 >= 0 && iy0 < Wl) ? 1.f : 0.f;
    float fy1 = (iy1 >= 0 && iy1 < Wl) ? 1.f : 0.f;
    int cx0 = min(max(ix0, 0), Wl - 1);
    int cx1 = min(max(ix1, 0), Wl - 1);
    int cy0 = min(max(iy0, 0), Wl - 1);
    int cy1 = min(max(iy1, 0), Wl - 1);
    int i00 = (Sl + cy0 * Wl + cx0) * 256;
    int i01 = (Sl + cy0 * Wl + cx1) * 256;
    int i10 = (Sl + cy1 * Wl + cx0) * 256;
    int i11 = (Sl + cy1 * Wl + cx1) * 256;
    float w00 = wy0 * wx0 * aw * (fy0 * fx0);
    float w01 = wy0 * wx1 * aw * (fy0 * fx1);
    float w10 = wy1 * wx0 * aw * (fy1 * fx0);
    float w11 = wy1 * wx1 * aw * (fy1 * fx1);

    const __half* vbase = value16 + (size_t)b * L_TOK * 256 + h * 32 + lane;

    float a = 0.0f;
#pragma unroll
    for (int p = 0; p < 16; p++) {
        int   j00 = __shfl_sync(0xFFFFFFFFu, i00, p);
        int   j01 = __shfl_sync(0xFFFFFFFFu, i01, p);
        int   j10 = __shfl_sync(0xFFFFFFFFu, i10, p);
        int   j11 = __shfl_sync(0xFFFFFFFFu, i11, p);
        float u00 = __shfl_sync(0xFFFFFFFFu, w00, p);
        float u01 = __shfl_sync(0xFFFFFFFFu, w01, p);
        float u10 = __shfl_sync(0xFFFFFFFFu, w10, p);
        float u11 = __shfl_sync(0xFFFFFFFFu, w11, p);
        float v00 = __half2float(vbase[j00]);
        float v01 = __half2float(vbase[j01]);
        float v10 = __half2float(vbase[j10]);
        float v11 = __half2float(vbase[j11]);
        a = fmaf(v00, u00, a);
        a = fmaf(v01, u01, a);
        a = fmaf(v10, u10, a);
        a = fmaf(v11, u11, a);
    }
    acc16[(size_t)bq * 256 + h * 32 + lane] = __float2half(a);
}

// ---------------- fused residual + LayerNorm (optional fp16 copy) ----------------
__global__ __launch_bounds__(256)
void ln_kernel(const float* __restrict__ a, const float* __restrict__ r,
               const float* __restrict__ g, const float* __restrict__ be,
               float* __restrict__ out, __half* __restrict__ out16)
{
    int row  = blockIdx.x * 8 + (threadIdx.x >> 5);
    int lane = threadIdx.x & 31;
    if (row >= M_TOT) return;

    const float4* pa = (const float4*)(a + (size_t)row * 256);
    const float4* pr = (const float4*)(r + (size_t)row * 256);
    float4 v0 = pa[lane],      w0 = pr[lane];
    float4 v1 = pa[32 + lane], w1 = pr[32 + lane];
    v0.x += w0.x; v0.y += w0.y; v0.z += w0.z; v0.w += w0.w;
    v1.x += w1.x; v1.y += w1.y; v1.z += w1.z; v1.w += w1.w;

    float ssum = v0.x + v0.y + v0.z + v0.w + v1.x + v1.y + v1.z + v1.w;
#pragma unroll
    for (int o = 16; o; o >>= 1) ssum += __shfl_xor_sync(0xFFFFFFFFu, ssum, o);
    float mu = ssum * (1.0f / 256.0f);

    float d0x = v0.x - mu, d0y = v0.y - mu, d0z = v0.z - mu, d0w = v0.w - mu;
    float d1x = v1.x - mu, d1y = v1.y - mu, d1z = v1.z - mu, d1w = v1.w - mu;
    float sq = d0x*d0x + d0y*d0y + d0z*d0z + d0w*d0w
             + d1x*d1x + d1y*d1y + d1z*d1z + d1w*d1w;
#pragma unroll
    for (int o = 16; o; o >>= 1) sq += __shfl_xor_sync(0xFFFFFFFFu, sq, o);
    float var = sq * (1.0f / 256.0f);
    float sc = rsqrtf(var + 1e-5f);

    const float4* pg = (const float4*)g;
    const float4* pb = (const float4*)be;
    float4 g0 = pg[lane], g1 = pg[32 + lane];
    float4 b0 = pb[lane], b1 = pb[32 + lane];

    float4 o0, o1;
    o0.x = d0x * sc * g0.x + b0.x;  o0.y = d0y * sc * g0.y + b0.y;
    o0.z = d0z * sc * g0.z + b0.z;  o0.w = d0w * sc * g0.w + b0.w;
    o1.x = d1x * sc * g1.x + b1.x;  o1.y = d1y * sc * g1.y + b1.y;
    o1.z = d1z * sc * g1.z + b1.z;  o1.w = d1w * sc * g1.w + b1.w;

    float4* po = (float4*)(out + (size_t)row * 256);
    po[lane]      = o0;
    po[32 + lane] = o1;

    if (out16) {
        __half2* ph = (__half2*)(out16 + (size_t)row * 256);
        ph[lane * 2 + 0]      = __floats2half2_rn(o0.x, o0.y);
        ph[lane * 2 + 1]      = __floats2half2_rn(o0.z, o0.w);
        ph[64 + lane * 2 + 0] = __floats2half2_rn(o1.x, o1.y);
        ph[64 + lane * 2 + 1] = __floats2half2_rn(o1.z, o1.w);
    }
}

// ---------------- launch ----------------
extern "C" void kernel_launch(void* const* d_in, const int* in_sizes, int n_in,
                              void* d_out, int out_size)
{
    const float* src        = (const float*)d_in[0];
    const float* src2       = (const float*)d_in[1];
    const float* pos        = (const float*)d_in[2];
    const float* memory_pos = (const float*)d_in[3];
    const float* value_w    = (const float*)d_in[4];
    const float* value_b    = (const float*)d_in[5];
    const float* off_w      = (const float*)d_in[6];
    const float* off_b      = (const float*)d_in[7];
    const float* aw_w       = (const float*)d_in[8];
    const float* aw_b       = (const float*)d_in[9];
    const float* out_w      = (const float*)d_in[10];
    const float* out_b      = (const float*)d_in[11];
    const float* ln_g       = (const float*)d_in[12];
    const float* ln_b       = (const float*)d_in[13];
    const float* lin1_w     = (const float*)d_in[14];
    const float* lin1_b     = (const float*)d_in[15];
    const float* lin2_w     = (const float*)d_in[16];
    const float* lin2_b     = (const float*)d_in[17];
    float* outp = (float*)d_out;

    __half *q16, *mem16, *value16, *acc16, *x16, *h16;
    __half *vw16, *offw16, *aww16, *outw16, *l1w16, *l2w16;
    float *offs, *awlog, *attn, *x, *ffn;
    cudaGetSymbolAddress((void**)&q16,    g_q16);
    cudaGetSymbolAddress((void**)&mem16,  g_mem16);
    cudaGetSymbolAddress((void**)&value16,g_value16);
    cudaGetSymbolAddress((void**)&offs,   g_offs);
    cudaGetSymbolAddress((void**)&awlog,  g_awlog);
    cudaGetSymbolAddress((void**)&acc16,  g_acc16);
    cudaGetSymbolAddress((void**)&attn,   g_attn);
    cudaGetSymbolAddress((void**)&x,      g_x);
    cudaGetSymbolAddress((void**)&x16,    g_x16);
    cudaGetSymbolAddress((void**)&h16,    g_h16);
    cudaGetSymbolAddress((void**)&ffn,    g_ffn);
    cudaGetSymbolAddress((void**)&vw16,   g_vw16);
    cudaGetSymbolAddress((void**)&offw16, g_offw16);
    cudaGetSymbolAddress((void**)&aww16,  g_aww16);
    cudaGetSymbolAddress((void**)&outw16, g_outw16);
    cudaGetSymbolAddress((void**)&l1w16,  g_l1w16);
    cudaGetSymbolAddress((void**)&l2w16,  g_l2w16);

    cudaFuncSetAttribute(hgemm_kernel<0,0>, cudaFuncAttributeMaxDynamicSharedMemorySize, SMEM_BYTES);
    cudaFuncSetAttribute(hgemm_kernel<0,1>, cudaFuncAttributeMaxDynamicSharedMemorySize, SMEM_BYTES);
    cudaFuncSetAttribute(hgemm_kernel<1,1>, cudaFuncAttributeMaxDynamicSharedMemorySize, SMEM_BYTES);

    transpose6_kernel<<<dim3(32, 32, 6), dim3(32, 8)>>>(
        value_w, off_w, aw_w, out_w, lin1_w, lin2_w,
        vw16, offw16, aww16, outw16, l1w16, l2w16);

    const int n4 = M_TOT * D_MODEL / 4;
    add2h2_kernel<<<(n4 + 255) / 256, 256>>>(src, pos, src2, memory_pos, q16, mem16, n4);

    dim3 blk(256);
    const int GY = (M_TOT + 127) / 128;     // 416
    dim3 g256(2, GY);
    dim3 g128(1, GY);
    dim3 g1024(8, GY);

    hgemm_kernel<0,1><<<g256, blk, SMEM_BYTES>>>(mem16, vw16,   value_b, value16, M_TOT, 256, 256);
    hgemm_kernel<0,0><<<g256, blk, SMEM_BYTES>>>(q16,   offw16, off_b,   offs,    M_TOT, 256, 256);
    hgemm_kernel<0,0><<<g128, blk, SMEM_BYTES>>>(q16,   aww16,  aw_b,    awlog,   M_TOT, 128, 256);

    deform_sample_kernel<<<M_TOT, 256>>>(value16, offs, awlog, acc16);

    hgemm_kernel<0,0><<<g256, blk, SMEM_BYTES>>>(acc16, outw16, out_b, attn, M_TOT, 256, 256);

    ln_kernel<<<(M_TOT + 7) / 8, 256>>>(attn, src, ln_g, ln_b, x, x16);

    hgemm_kernel<1,1><<<g1024, blk, SMEM_BYTES>>>(x16, l1w16, lin1_b, h16, M_TOT, 1024, 256);
    hgemm_kernel<0,0><<<g256,  blk, SMEM_BYTES>>>(h16, l2w16, lin2_b, ffn,  M_TOT, 256, 1024);

    ln_kernel<<<(M_TOT + 7) / 8, 256>>>(ffn, x, ln_g, ln_b, outp, (half*)nullptr);
}

// round 17
// speedup vs baseline: 1.4006x; 1.0737x over previous
#include <cuda_runtime.h>
#include <cuda_fp16.h>
#include <math.h>
#include <stdint.h>

// ---------------- problem constants ----------------
#define D_MODEL   256
#define N_HEADS   8
#define HEAD_DIM  32
#define L_TOK     13294
#define BATCH     4
#define M_TOT     (BATCH * L_TOK)   // 53176
#define D_FFN     1024

// ---------------- scratch (static device globals; no allocations) ----------------
__device__ __half g_q16   [(size_t)M_TOT * D_MODEL];
__device__ __half g_mem16 [(size_t)M_TOT * D_MODEL];
__device__ __half g_value16[(size_t)M_TOT * D_MODEL];
__device__ float  g_offs  [(size_t)M_TOT * D_MODEL];
__device__ float  g_awlog [(size_t)M_TOT * 128];
__device__ __half g_acc16 [(size_t)M_TOT * D_MODEL];
__device__ float  g_attn  [(size_t)M_TOT * D_MODEL];
__device__ float  g_x     [(size_t)M_TOT * D_MODEL];
__device__ __half g_x16   [(size_t)M_TOT * D_MODEL];
__device__ __half g_h16   [(size_t)M_TOT * D_FFN];
__device__ float  g_ffn   [(size_t)M_TOT * D_MODEL];
// transposed fp16 weights [N][K]
__device__ __half g_vw16  [256 * 256];
__device__ __half g_offw16[256 * 256];
__device__ __half g_aww16 [128 * 256];
__device__ __half g_outw16[256 * 256];
__device__ __half g_l1w16 [1024 * 256];
__device__ __half g_l2w16 [256 * 1024];

// ---------------- helpers ----------------
__device__ __forceinline__ void mma_f16(float* c, const uint32_t* a, const uint32_t* b) {
    asm volatile(
        "mma.sync.aligned.m16n8k16.row.col.f32.f16.f16.f32 "
        "{%0,%1,%2,%3}, {%4,%5,%6,%7}, {%8,%9}, {%0,%1,%2,%3};\n"
        : "+f"(c[0]), "+f"(c[1]), "+f"(c[2]), "+f"(c[3])
        : "r"(a[0]), "r"(a[1]), "r"(a[2]), "r"(a[3]),
          "r"(b[0]), "r"(b[1]));
}
__device__ __forceinline__ void ldsm_x4(uint32_t* r, uint32_t saddr) {
    asm volatile("ldmatrix.sync.aligned.m8n8.x4.shared.b16 {%0,%1,%2,%3}, [%4];\n"
                 : "=r"(r[0]), "=r"(r[1]), "=r"(r[2]), "=r"(r[3]) : "r"(saddr));
}
__device__ __forceinline__ void cp_async16(uint32_t smem_addr, const void* gptr) {
    asm volatile("cp.async.ca.shared.global [%0], [%1], 16;\n"
                 :: "r"(smem_addr), "l"(gptr));
}
__device__ __forceinline__ void cp_async16_guard(uint32_t smem_addr, const void* gptr, int src_bytes) {
    asm volatile("cp.async.ca.shared.global [%0], [%1], 16, %2;\n"
                 :: "r"(smem_addr), "l"(gptr), "r"(src_bytes));
}
__device__ __forceinline__ void cp_commit() { asm volatile("cp.async.commit_group;\n"); }
template<int N>
__device__ __forceinline__ void cp_wait() { asm volatile("cp.async.wait_group %0;\n" :: "n"(N)); }

// ---------------- fused adds: q16 = src+pos, mem16 = src2+memory_pos ----------------
__global__ void add2h2_kernel(const float* __restrict__ a0, const float* __restrict__ b0,
                              const float* __restrict__ a1, const float* __restrict__ b1,
                              __half* __restrict__ o0, __half* __restrict__ o1, int n4)
{
    int i = blockIdx.x * blockDim.x + threadIdx.x;
    if (i < n4) {
        float4 x = ((const float4*)a0)[i];
        float4 y = ((const float4*)b0)[i];
        ((__half2*)o0)[i * 2 + 0] = __floats2half2_rn(x.x + y.x, x.y + y.y);
        ((__half2*)o0)[i * 2 + 1] = __floats2half2_rn(x.z + y.z, x.w + y.w);
        float4 u = ((const float4*)a1)[i];
        float4 v = ((const float4*)b1)[i];
        ((__half2*)o1)[i * 2 + 0] = __floats2half2_rn(u.x + v.x, u.y + v.y);
        ((__half2*)o1)[i * 2 + 1] = __floats2half2_rn(u.z + v.z, u.w + v.w);
    }
}

// ---------------- all 6 weight transposes fp32[K][N] -> fp16[N][K], one launch ----------------
__global__ void transpose6_kernel(
    const float* __restrict__ i0, const float* __restrict__ i1, const float* __restrict__ i2,
    const float* __restrict__ i3, const float* __restrict__ i4, const float* __restrict__ i5,
    __half* __restrict__ o0, __half* __restrict__ o1, __half* __restrict__ o2,
    __half* __restrict__ o3, __half* __restrict__ o4, __half* __restrict__ o5)
{
    const float* in; __half* out; int K, N;
    switch (blockIdx.z) {
        case 0: in = i0; out = o0; K = 256;  N = 256;  break;
        case 1: in = i1; out = o1; K = 256;  N = 256;  break;
        case 2: in = i2; out = o2; K = 256;  N = 128;  break;
        case 3: in = i3; out = o3; K = 256;  N = 256;  break;
        case 4: in = i4; out = o4; K = 256;  N = 1024; break;
        default: in = i5; out = o5; K = 1024; N = 256; break;
    }
    int n0 = blockIdx.x * 32, k0 = blockIdx.y * 32;
    if (n0 >= N || k0 >= K) return;

    __shared__ float t[32][33];
    int tx = threadIdx.x, ty = threadIdx.y;      // 32 x 8
#pragma unroll
    for (int i = ty; i < 32; i += 8)
        t[i][tx] = in[(size_t)(k0 + i) * N + n0 + tx];
    __syncthreads();
#pragma unroll
    for (int i = ty; i < 32; i += 8)
        out[(size_t)(n0 + i) * K + k0 + tx] = __float2half(t[tx][i]);
}

// ---------------- FP16 tensor-core GEMM, BK=64, 2-stage cp.async, ldmatrix ----------------
// Block 128x128x64, 8 warps (2m x 4n), warp tile 64x32, m16n8k16, fp32 accum.
// LDH=72 halves (144B rows): 16B-aligned chunks; 8-row LDSM addresses hit banks
// 4r (conflict-free). Half the barriers of BK=32, 2x MMA per sync.
#define LDH 72
#define ASZH (128 * LDH)
#define BSZH (128 * LDH)
#define SMEM_BYTES ((2 * ASZH + 2 * BSZH) * 2)

template<int RELU, int HOUT>
__global__ __launch_bounds__(256)
void hgemm_kernel(const __half* __restrict__ A, const __half* __restrict__ Wt,
                  const float* __restrict__ bias, void* __restrict__ Cout,
                  int M, int N, int K)
{
    extern __shared__ __half smem[];
    __half* As = smem;                 // [2][128][LDH]
    __half* Bs = smem + 2 * ASZH;      // [2][128][LDH]

    const int tid  = threadIdx.x;
    const int lane = tid & 31;
    const int warp = tid >> 5;
    const int wm = (warp >> 2) * 64;
    const int wn = (warp & 3) * 32;
    const int grp = lane >> 2;
    const int tg  = lane & 3;
    const int m0 = blockIdx.y * 128;
    const int n0 = blockIdx.x * 128;

    uint32_t As_u = (uint32_t)__cvta_generic_to_shared(As);
    uint32_t Bs_u = (uint32_t)__cvta_generic_to_shared(Bs);

    float acc[4][4][4];
#pragma unroll
    for (int mi = 0; mi < 4; mi++)
#pragma unroll
        for (int ni = 0; ni < 4; ni++)
#pragma unroll
            for (int e = 0; e < 4; e++) acc[mi][ni][e] = 0.0f;

    const int T = K / 64;

    auto fill = [&](int st, int k0) {
        uint32_t abase = As_u + (uint32_t)(st * ASZH * 2);
        uint32_t bbase = Bs_u + (uint32_t)(st * BSZH * 2);
        // A: 128 rows x 8 chunks(8 halves=16B) = 1024 / 256 thr = 4 each
#pragma unroll
        for (int it = 0; it < 4; it++) {
            int idx = tid + it * 256;
            int r  = idx >> 3;
            int kc = idx & 7;
            int valid = (m0 + r < M) ? 16 : 0;
            cp_async16_guard(abase + (uint32_t)((r * LDH + kc * 8) * 2),
                             A + (size_t)(m0 + r) * K + k0 + kc * 8, valid);
        }
        // B: 128 n-rows x 8 chunks
#pragma unroll
        for (int it = 0; it < 4; it++) {
            int idx = tid + it * 256;
            int r  = idx >> 3;
            int kc = idx & 7;
            cp_async16(bbase + (uint32_t)((r * LDH + kc * 8) * 2),
                       Wt + (size_t)(n0 + r) * K + k0 + kc * 8);
        }
        cp_commit();
    };

    fill(0, 0);

    for (int t = 0; t < T; t++) {
        if (t + 1 < T) {
            fill((t + 1) & 1, (t + 1) * 64);
            cp_wait<1>();
        } else {
            cp_wait<0>();
        }
        __syncthreads();

        const uint32_t As_sb = As_u + (uint32_t)((t & 1) * ASZH * 2);
        const uint32_t Bs_sb = Bs_u + (uint32_t)((t & 1) * BSZH * 2);

#pragma unroll
        for (int ks = 0; ks < 4; ks++) {
            const int kb = ks * 16;
            uint32_t a[4][4], b[4][2];
#pragma unroll
            for (int mi = 0; mi < 4; mi++) {
                uint32_t ad = As_sb + (uint32_t)(((wm + mi * 16 + (lane & 15)) * LDH
                                                 + kb + (lane >> 4) * 8) * 2);
                ldsm_x4(a[mi], ad);
            }
            // B: 2x ldsm_x4, each covers ni pair {np, np+1}
#pragma unroll
            for (int np = 0; np < 4; np += 2) {
                uint32_t bq[4];
                uint32_t bd = Bs_sb + (uint32_t)(((wn + np * 8 + (lane & 7)
                                                  + ((lane >> 4) & 1) * 8) * LDH
                                                 + kb + ((lane >> 3) & 1) * 8) * 2);
                ldsm_x4(bq, bd);
                b[np][0]     = bq[0]; b[np][1]     = bq[1];
                b[np + 1][0] = bq[2]; b[np + 1][1] = bq[3];
            }
#pragma unroll
            for (int mi = 0; mi < 4; mi++)
#pragma unroll
                for (int ni = 0; ni < 4; ni++)
                    mma_f16(acc[mi][ni], a[mi], b[ni]);
        }
        __syncthreads();
    }

    // epilogue
#pragma unroll
    for (int mi = 0; mi < 4; mi++) {
        int r0 = m0 + wm + mi * 16 + grp;
        int r1 = r0 + 8;
#pragma unroll
        for (int ni = 0; ni < 4; ni++) {
            int col = n0 + wn + ni * 8 + tg * 2;
            float bx = bias[col], by = bias[col + 1];
            float* cc = acc[mi][ni];
            float v0x = cc[0] + bx, v0y = cc[1] + by;
            float v1x = cc[2] + bx, v1y = cc[3] + by;
            if (RELU) {
                v0x = fmaxf(v0x, 0.f); v0y = fmaxf(v0y, 0.f);
                v1x = fmaxf(v1x, 0.f); v1y = fmaxf(v1y, 0.f);
            }
            if (HOUT) {
                __half* C16 = (__half*)Cout;
                if (r0 < M) *(__half2*)(C16 + (size_t)r0 * N + col) = __floats2half2_rn(v0x, v0y);
                if (r1 < M) *(__half2*)(C16 + (size_t)r1 * N + col) = __floats2half2_rn(v1x, v1y);
            } else {
                float* C = (float*)Cout;
                if (r0 < M) { float2 o; o.x = v0x; o.y = v0y; *(float2*)(C + (size_t)r0 * N + col) = o; }
                if (r1 < M) { float2 o; o.x = v1x; o.y = v1y; *(float2*)(C + (size_t)r1 * N + col) = o; }
            }
        }
    }
}

// ---------------- deformable attention sampling (softmax fused) ----------------
__global__ __launch_bounds__(256)
void deform_sample_kernel(const __half* __restrict__ value16,
                          const float* __restrict__ offs,
                          const float* __restrict__ awlog,
                          __half* __restrict__ acc16)
{
    const int bq = blockIdx.x;
    const int h    = threadIdx.x >> 5;
    const int lane = threadIdx.x & 31;

    const int b  = bq / L_TOK;
    const int qi = bq - b * L_TOK;

    int ql, s;
    if      (qi < 10000) { ql = 0; s = 0;     }
    else if (qi < 12500) { ql = 1; s = 10000; }
    else if (qi < 13125) { ql = 2; s = 12500; }
    else                 { ql = 3; s = 13125; }
    const int LH4[4] = {100, 50, 25, 13};
    const int LS[4] = {0, 10000, 12500, 13125};
    const int Wq = LH4[ql];
    int rem = qi - s;
    float refx = ((rem % Wq) + 0.5f) / (float)Wq;
    float refy = ((rem / Wq) + 0.5f) / (float)Wq;

    const int pidx = lane & 15;
    const int l  = pidx >> 2;
    const int Wl = LH4[l];
    const int Sl = LS[l];
    const float Wf = (float)Wl;

    float lg = awlog[(size_t)bq * 128 + h * 16 + pidx];
    float m = lg;
#pragma unroll
    for (int o = 8; o; o >>= 1) m = fmaxf(m, __shfl_xor_sync(0xFFFFFFFFu, m, o));
    float ev = expf(lg - m);
    float ssum = ev;
#pragma unroll
    for (int o = 8; o; o >>= 1) ssum += __shfl_xor_sync(0xFFFFFFFFu, ssum, o);
    float aw = ev / ssum;

    float2 oxy = *(const float2*)(offs + (size_t)bq * 256 + h * 32 + pidx * 2);

    float locx = refx + oxy.x / Wf;
    float locy = refy + oxy.y / Wf;
    float x = locx * Wf - 0.5f;
    float y = locy * Wf - 0.5f;
    float x0f = floorf(x), y0f = floorf(y);
    float wx1 = x - x0f,   wy1 = y - y0f;
    float wx0 = 1.0f - wx1, wy0 = 1.0f - wy1;
    int ix0 = (int)x0f, iy0 = (int)y0f;
    int ix1 = ix0 + 1,  iy1 = iy0 + 1;
    float fx0 = (ix0 >= 0 && ix0 < Wl) ? 1.f : 0.f;
    float fx1 = (ix1 >= 0 && ix1 < Wl) ? 1.f : 0.f;
    float fy0 = (iy0 >= 0 && iy0 < Wl) ? 1.f : 0.f;
    float fy1 = (iy1 >= 0 && iy1 < Wl) ? 1.f : 0.f;
    int cx0 = min(max(ix0, 0), Wl - 1);
    int cx1 = min(max(ix1, 0), Wl - 1);
    int cy0 = min(max(iy0, 0), Wl - 1);
    int cy1 = min(max(iy1, 0), Wl - 1);
    int i00 = (Sl + cy0 * Wl + cx0) * 256;
    int i01 = (Sl + cy0 * Wl + cx1) * 256;
    int i10 = (Sl + cy1 * Wl + cx0) * 256;
    int i11 = (Sl + cy1 * Wl + cx1) * 256;
    float w00 = wy0 * wx0 * aw * (fy0 * fx0);
    float w01 = wy0 * wx1 * aw * (fy0 * fx1);
    float w10 = wy1 * wx0 * aw * (fy1 * fx0);
    float w11 = wy1 * wx1 * aw * (fy1 * fx1);

    const __half* vbase = value16 + (size_t)b * L_TOK * 256 + h * 32 + lane;

    float a = 0.0f;
#pragma unroll
    for (int p = 0; p < 16; p++) {
        int   j00 = __shfl_sync(0xFFFFFFFFu, i00, p);
        int   j01 = __shfl_sync(0xFFFFFFFFu, i01, p);
        int   j10 = __shfl_sync(0xFFFFFFFFu, i10, p);
        int   j11 = __shfl_sync(0xFFFFFFFFu, i11, p);
        float u00 = __shfl_sync(0xFFFFFFFFu, w00, p);
        float u01 = __shfl_sync(0xFFFFFFFFu, w01, p);
        float u10 = __shfl_sync(0xFFFFFFFFu, w10, p);
        float u11 = __shfl_sync(0xFFFFFFFFu, w11, p);
        float v00 = __half2float(vbase[j00]);
        float v01 = __half2float(vbase[j01]);
        float v10 = __half2float(vbase[j10]);
        float v11 = __half2float(vbase[j11]);
        a = fmaf(v00, u00, a);
        a = fmaf(v01, u01, a);
        a = fmaf(v10, u10, a);
        a = fmaf(v11, u11, a);
    }
    acc16[(size_t)bq * 256 + h * 32 + lane] = __float2half(a);
}

// ---------------- fused residual + LayerNorm (optional fp16 copy) ----------------
__global__ __launch_bounds__(256)
void ln_kernel(const float* __restrict__ a, const float* __restrict__ r,
               const float* __restrict__ g, const float* __restrict__ be,
               float* __restrict__ out, __half* __restrict__ out16)
{
    int row  = blockIdx.x * 8 + (threadIdx.x >> 5);
    int lane = threadIdx.x & 31;
    if (row >= M_TOT) return;

    const float4* pa = (const float4*)(a + (size_t)row * 256);
    const float4* pr = (const float4*)(r + (size_t)row * 256);
    float4 v0 = pa[lane],      w0 = pr[lane];
    float4 v1 = pa[32 + lane], w1 = pr[32 + lane];
    v0.x += w0.x; v0.y += w0.y; v0.z += w0.z; v0.w += w0.w;
    v1.x += w1.x; v1.y += w1.y; v1.z += w1.z; v1.w += w1.w;

    float ssum = v0.x + v0.y + v0.z + v0.w + v1.x + v1.y + v1.z + v1.w;
#pragma unroll
    for (int o = 16; o; o >>= 1) ssum += __shfl_xor_sync(0xFFFFFFFFu, ssum, o);
    float mu = ssum * (1.0f / 256.0f);

    float d0x = v0.x - mu, d0y = v0.y - mu, d0z = v0.z - mu, d0w = v0.w - mu;
    float d1x = v1.x - mu, d1y = v1.y - mu, d1z = v1.z - mu, d1w = v1.w - mu;
    float sq = d0x*d0x + d0y*d0y + d0z*d0z + d0w*d0w
             + d1x*d1x + d1y*d1y + d1z*d1z + d1w*d1w;
#pragma unroll
    for (int o = 16; o; o >>= 1) sq += __shfl_xor_sync(0xFFFFFFFFu, sq, o);
    float var = sq * (1.0f / 256.0f);
    float sc = rsqrtf(var + 1e-5f);

    const float4* pg = (const float4*)g;
    const float4* pb = (const float4*)be;
    float4 g0 = pg[lane], g1 = pg[32 + lane];
    float4 b0 = pb[lane], b1 = pb[32 + lane];

    float4 o0, o1;
    o0.x = d0x * sc * g0.x + b0.x;  o0.y = d0y * sc * g0.y + b0.y;
    o0.z = d0z * sc * g0.z + b0.z;  o0.w = d0w * sc * g0.w + b0.w;
    o1.x = d1x * sc * g1.x + b1.x;  o1.y = d1y * sc * g1.y + b1.y;
    o1.z = d1z * sc * g1.z + b1.z;  o1.w = d1w * sc * g1.w + b1.w;

    float4* po = (float4*)(out + (size_t)row * 256);
    po[lane]      = o0;
    po[32 + lane] = o1;

    if (out16) {
        __half2* ph = (__half2*)(out16 + (size_t)row * 256);
        ph[lane * 2 + 0]      = __floats2half2_rn(o0.x, o0.y);
        ph[lane * 2 + 1]      = __floats2half2_rn(o0.z, o0.w);
        ph[64 + lane * 2 + 0] = __floats2half2_rn(o1.x, o1.y);
        ph[64 + lane * 2 + 1] = __floats2half2_rn(o1.z, o1.w);
    }
}

// ---------------- launch ----------------
extern "C" void kernel_launch(void* const* d_in, const int* in_sizes, int n_in,
                              void* d_out, int out_size)
{
    const float* src        = (const float*)d_in[0];
    const float* src2       = (const float*)d_in[1];
    const float* pos        = (const float*)d_in[2];
    const float* memory_pos = (const float*)d_in[3];
    const float* value_w    = (const float*)d_in[4];
    const float* value_b    = (const float*)d_in[5];
    const float* off_w      = (const float*)d_in[6];
    const float* off_b      = (const float*)d_in[7];
    const float* aw_w       = (const float*)d_in[8];
    const float* aw_b       = (const float*)d_in[9];
    const float* out_w      = (const float*)d_in[10];
    const float* out_b      = (const float*)d_in[11];
    const float* ln_g       = (const float*)d_in[12];
    const float* ln_b       = (const float*)d_in[13];
    const float* lin1_w     = (const float*)d_in[14];
    const float* lin1_b     = (const float*)d_in[15];
    const float* lin2_w     = (const float*)d_in[16];
    const float* lin2_b     = (const float*)d_in[17];
    float* outp = (float*)d_out;

    __half *q16, *mem16, *value16, *acc16, *x16, *h16;
    __half *vw16, *offw16, *aww16, *outw16, *l1w16, *l2w16;
    float *offs, *awlog, *attn, *x, *ffn;
    cudaGetSymbolAddress((void**)&q16,    g_q16);
    cudaGetSymbolAddress((void**)&mem16,  g_mem16);
    cudaGetSymbolAddress((void**)&value16,g_value16);
    cudaGetSymbolAddress((void**)&offs,   g_offs);
    cudaGetSymbolAddress((void**)&awlog,  g_awlog);
    cudaGetSymbolAddress((void**)&acc16,  g_acc16);
    cudaGetSymbolAddress((void**)&attn,   g_attn);
    cudaGetSymbolAddress((void**)&x,      g_x);
    cudaGetSymbolAddress((void**)&x16,    g_x16);
    cudaGetSymbolAddress((void**)&h16,    g_h16);
    cudaGetSymbolAddress((void**)&ffn,    g_ffn);
    cudaGetSymbolAddress((void**)&vw16,   g_vw16);
    cudaGetSymbolAddress((void**)&offw16, g_offw16);
    cudaGetSymbolAddress((void**)&aww16,  g_aww16);
    cudaGetSymbolAddress((void**)&outw16, g_outw16);
    cudaGetSymbolAddress((void**)&l1w16,  g_l1w16);
    cudaGetSymbolAddress((void**)&l2w16,  g_l2w16);

    cudaFuncSetAttribute(hgemm_kernel<0,0>, cudaFuncAttributeMaxDynamicSharedMemorySize, SMEM_BYTES);
    cudaFuncSetAttribute(hgemm_kernel<0,1>, cudaFuncAttributeMaxDynamicSharedMemorySize, SMEM_BYTES);
    cudaFuncSetAttribute(hgemm_kernel<1,1>, cudaFuncAttributeMaxDynamicSharedMemorySize, SMEM_BYTES);

    transpose6_kernel<<<dim3(32, 32, 6), dim3(32, 8)>>>(
        value_w, off_w, aw_w, out_w, lin1_w, lin2_w,
        vw16, offw16, aww16, outw16, l1w16, l2w16);

    const int n4 = M_TOT * D_MODEL / 4;
    add2h2_kernel<<<(n4 + 255) / 256, 256>>>(src, pos, src2, memory_pos, q16, mem16, n4);

    dim3 blk(256);
    const int GY = (M_TOT + 127) / 128;     // 416
    dim3 g256(2, GY);
    dim3 g128(1, GY);
    dim3 g1024(8, GY);

    hgemm_kernel<0,1><<<g256, blk, SMEM_BYTES>>>(mem16, vw16,   value_b, value16, M_TOT, 256, 256);
    hgemm_kernel<0,0><<<g256, blk, SMEM_BYTES>>>(q16,   offw16, off_b,   offs,    M_TOT, 256, 256);
    hgemm_kernel<0,0><<<g128, blk, SMEM_BYTES>>>(q16,   aww16,  aw_b,    awlog,   M_TOT, 128, 256);

    deform_sample_kernel<<<M_TOT, 256>>>(value16, offs, awlog, acc16);

    hgemm_kernel<0,0><<<g256, blk, SMEM_BYTES>>>(acc16, outw16, out_b, attn, M_TOT, 256, 256);

    ln_kernel<<<(M_TOT + 7) / 8, 256>>>(attn, src, ln_g, ln_b, x, x16);

    hgemm_kernel<1,1><<<g1024, blk, SMEM_BYTES>>>(x16, l1w16, lin1_b, h16, M_TOT, 1024, 256);
    hgemm_kernel<0,0><<<g256,  blk, SMEM_BYTES>>>(h16, l2w16, lin2_b, ffn,  M_TOT, 256, 1024);

    ln_kernel<<<(M_TOT + 7) / 8, 256>>>(ffn, x, ln_g, ln_b, outp, (half*)nullptr);
}